// round 9
// baseline (speedup 1.0000x reference)
#include <cuda_runtime.h>
#include <mma.h>
#include <math.h>
#include <stdint.h>

using namespace nvcuda;

#define N_TOK 4096
#define D_DIM 2048
#define F_DIM 8192
#define E_EXP 8
#define R_RANK 8
#define SCALING 2.0f

#define BM 128
#define BN 128
#define BK 16
#define TM 8
#define TN 8

// ---------------- scratch ----------------------------------------------------
__device__ float g_buf[(size_t)N_TOK * F_DIM];
__device__ float h_buf[2ull * N_TOK * F_DIM];
__device__ float z1c[N_TOK * 2 * R_RANK];
__device__ float z2s[N_TOK * 2 * R_RANK];
__device__ int   eidx[N_TOK * 2];
__device__ float ew[N_TOK * 2];
__device__ float wsum_buf[N_TOK];
__device__ int gf1, gf2;

__device__ __forceinline__ float gelu_new(float x) {
    float x3 = x * x * x;
    float t = tanhf(0.7978845608028654f * (x + 0.044715f * x3));
    return 0.5f * x * (1.0f + t);
}

// ============================================================================
// router — verbatim R1
// ============================================================================
__global__ __launch_bounds__(256) void router_kernel(
    const float* __restrict__ x, const float* __restrict__ Wr,
    const float* __restrict__ br, const float* __restrict__ A1)
{
    int n = blockIdx.x;
    int tid = threadIdx.x;
    __shared__ float xs[D_DIM];
    __shared__ float red[16][8];
    __shared__ int s_idx[2];

    for (int d = tid; d < D_DIM; d += 256) xs[d] = x[(size_t)n * D_DIM + d];
    __syncthreads();

    float acc[E_EXP];
#pragma unroll
    for (int e = 0; e < E_EXP; e++) acc[e] = 0.f;
    for (int d = tid; d < D_DIM; d += 256) {
        float xv = xs[d];
#pragma unroll
        for (int e = 0; e < E_EXP; e++) acc[e] += xv * Wr[e * D_DIM + d];
    }
#pragma unroll
    for (int e = 0; e < E_EXP; e++) {
        float v = acc[e];
        for (int o = 16; o > 0; o >>= 1) v += __shfl_down_sync(0xffffffffu, v, o);
        if ((tid & 31) == 0) red[e][tid >> 5] = v;
    }
    __syncthreads();

    if (tid == 0) {
        float lg[E_EXP];
#pragma unroll
        for (int e = 0; e < E_EXP; e++) {
            float v = 0.f;
#pragma unroll
            for (int w = 0; w < 8; w++) v += red[e][w];
            lg[e] = v + br[e];
        }
        float mx = lg[0];
#pragma unroll
        for (int e = 1; e < E_EXP; e++) mx = fmaxf(mx, lg[e]);
        float p[E_EXP], se = 0.f;
#pragma unroll
        for (int e = 0; e < E_EXP; e++) { p[e] = expf(lg[e] - mx); se += p[e]; }
        float inv = 1.0f / se;
#pragma unroll
        for (int e = 0; e < E_EXP; e++) p[e] *= inv;
        int i0 = 0;
#pragma unroll
        for (int e = 1; e < E_EXP; e++) if (p[e] > p[i0]) i0 = e;
        int i1 = -1;
#pragma unroll
        for (int e = 0; e < E_EXP; e++) {
            if (e == i0) continue;
            if (i1 < 0 || p[e] > p[i1]) i1 = e;
        }
        s_idx[0] = i0; s_idx[1] = i1;
        eidx[2 * n] = i0; eidx[2 * n + 1] = i1;
        ew[2 * n] = p[i0]; ew[2 * n + 1] = p[i1];
        wsum_buf[n] = p[i0] + p[i1];
    }
    __syncthreads();

    int e0 = s_idx[0], e1 = s_idx[1];
    float u[16];
#pragma unroll
    for (int i = 0; i < 16; i++) u[i] = 0.f;
    for (int d = tid; d < D_DIM; d += 256) {
        float xv = xs[d];
#pragma unroll
        for (int r = 0; r < R_RANK; r++) {
            u[r]     += xv * A1[((size_t)e0 * R_RANK + r) * D_DIM + d];
            u[8 + r] += xv * A1[((size_t)e1 * R_RANK + r) * D_DIM + d];
        }
    }
    __syncthreads();
#pragma unroll
    for (int i = 0; i < 16; i++) {
        float v = u[i];
        for (int o = 16; o > 0; o >>= 1) v += __shfl_down_sync(0xffffffffu, v, o);
        if ((tid & 31) == 0) red[i][tid >> 5] = v;
    }
    __syncthreads();
    if (tid < 16) {
        float v = 0.f;
#pragma unroll
        for (int w = 0; w < 8; w++) v += red[tid][w];
        z1c[n * 16 + tid] = v * SCALING;
    }
}

// ============================================================================
// tf32 GEMM machinery (the construct verified in Round 8)
// ============================================================================
typedef wmma::fragment<wmma::matrix_a, 16,16,8, wmma::precision::tf32, wmma::row_major> TFA;
typedef wmma::fragment<wmma::matrix_b, 16,16,8, wmma::precision::tf32, wmma::col_major> TFB;
typedef wmma::fragment<wmma::accumulator, 16,16,8, float> TFC;

// 128 rows x 16 cols fp32 tile; smem stride 20 floats
__device__ __forceinline__ void ldg_tile(float4* r, const float* g, size_t stride, int tid){
#pragma unroll
    for (int i=0;i<2;i++){
        int idx = tid + i*256;
        int row = idx>>2, c = (idx&3)*4;
        r[i] = *(const float4*)(g + (size_t)row*stride + c);
    }
}
__device__ __forceinline__ void sts_tile(float* s, const float4* r, int tid){
#pragma unroll
    for (int i=0;i<2;i++){
        int idx = tid + i*256;
        int row = idx>>2, c = (idx&3)*4;
        *(float4*)(s + row*20 + c) = r[i];
    }
}

// Mainloop: C[128,128] += A[128,K] * B[128,K]^T with tf32 x3 hi/lo passes.
// smem: double-buffered A|B tiles (2*(10240+10240) = 40960 B).
__device__ __forceinline__ void gemm_tf32(
    TFC (&acc)[2][4],
    const float* Ag, const float* Bg, size_t K, int nch,
    float* smem)
{
    const int tid = threadIdx.x, wid = tid>>5;
    const int wr = wid & 3, wc = wid >> 2;     // 4 M-warps x 2 N-warps
#pragma unroll
    for (int i=0;i<2;i++)
#pragma unroll
    for (int j=0;j<4;j++) wmma::fill_fragment(acc[i][j], 0.f);

    float4 ra[2], rb[2];
    ldg_tile(ra, Ag, K, tid);
    ldg_tile(rb, Bg, K, tid);
    sts_tile(smem,        ra, tid);
    sts_tile(smem + 2560, rb, tid);
    __syncthreads();

    for (int c = 0; c < nch; c++){
        if (c+1 < nch){
            ldg_tile(ra, Ag + (size_t)(c+1)*16, K, tid);
            ldg_tile(rb, Bg + (size_t)(c+1)*16, K, tid);
        }
        const float* sA = smem + (c&1)*5120;
        const float* sB = sA + 2560;
#pragma unroll
        for (int k8 = 0; k8 < 2; k8++){
            TFA ah[2], al[2];
            TFB bh[4], bl[4];
#pragma unroll
            for (int i=0;i<2;i++){
                TFA t;
                wmma::load_matrix_sync(t, sA + (wr*32 + i*16)*20 + k8*8, 20);
#pragma unroll
                for (int e=0;e<t.num_elements;e++){
                    float f = t.x[e];
                    float h = wmma::__float_to_tf32(f);
                    ah[i].x[e] = h;
                    al[i].x[e] = wmma::__float_to_tf32(f - h);
                }
            }
#pragma unroll
            for (int j=0;j<4;j++){
                TFB t;
                wmma::load_matrix_sync(t, sB + (wc*64 + j*16)*20 + k8*8, 20);
#pragma unroll
                for (int e=0;e<t.num_elements;e++){
                    float f = t.x[e];
                    float h = wmma::__float_to_tf32(f);
                    bh[j].x[e] = h;
                    bl[j].x[e] = wmma::__float_to_tf32(f - h);
                }
            }
#pragma unroll
            for (int i=0;i<2;i++)
#pragma unroll
            for (int j=0;j<4;j++){
                wmma::mma_sync(acc[i][j], ah[i], bh[j], acc[i][j]);
                wmma::mma_sync(acc[i][j], ah[i], bl[j], acc[i][j]);
                wmma::mma_sync(acc[i][j], al[i], bh[j], acc[i][j]);
            }
        }
        if (c+1 < nch){
            float* d = smem + ((c+1)&1)*5120;
            sts_tile(d,        ra, tid);
            sts_tile(d + 2560, rb, tid);
        }
        __syncthreads();
    }
}

// ============================================================================
// fc1 tf32: C = x @ W1^T, epilogue: +b1, LoRA1, gelu -> h0,h1,g (fp32)
// ============================================================================
__global__ __launch_bounds__(256) void fc1_tf32(
    const float* __restrict__ x, const float* __restrict__ W1,
    const float* __restrict__ b1, const float* __restrict__ B1)
{
    __shared__ __align__(16) float smem[10240];  // 40960 B
    int bn = blockIdx.x, bm = blockIdx.y;
    int tid = threadIdx.x, wid = tid>>5, wr = wid&3, wc = wid>>2;
    TFC acc[2][4];

    gemm_tf32(acc, x + (size_t)bm*128*D_DIM, W1 + (size_t)bn*128*D_DIM,
              D_DIM, D_DIM/16, smem);

    float* Cs = smem;   // 64 rows x 136 stride = 34816 B
    for (int r = 0; r < 2; r++){
        __syncthreads();
        if ((wr >> 1) == r){
            int rl = (wr & 1) * 32;
#pragma unroll
            for (int i=0;i<2;i++)
#pragma unroll
            for (int j=0;j<4;j++)
                wmma::store_matrix_sync(Cs + (size_t)(rl+i*16)*136 + wc*64 + j*16,
                                        acc[i][j], 136, wmma::mem_row_major);
        }
        __syncthreads();

        int row_l = tid >> 2;
        int n = bm*128 + r*64 + row_l;
        int c0 = (tid & 3) * 32;
        int e0 = eidx[2*n], e1 = eidx[2*n+1];
        float w0 = ew[2*n], w1w = ew[2*n+1];
        float z0[8], z1[8];
#pragma unroll
        for (int q=0;q<8;q++){ z0[q]=z1c[n*16+q]; z1[q]=z1c[n*16+8+q]; }
        const float* crow = &Cs[(size_t)row_l*136];
        for (int jj = 0; jj < 32; jj += 2){
            int col = c0 + jj;
            int f = bn*128 + col;
            float ca = crow[col]   + b1[f];
            float cb = crow[col+1] + b1[f+1];
            const float4* q0 = (const float4*)&B1[((size_t)e0*F_DIM + f)*R_RANK];
            const float4* q1 = (const float4*)&B1[((size_t)e1*F_DIM + f)*R_RANK];
            float l0a=0.f,l0b=0.f,l1a=0.f,l1b=0.f;
#pragma unroll
            for (int q=0;q<2;q++){
                float4 u0=q0[q], u2=q0[2+q], v0=q1[q], v2=q1[2+q];
                l0a += z0[q*4+0]*u0.x + z0[q*4+1]*u0.y + z0[q*4+2]*u0.z + z0[q*4+3]*u0.w;
                l0b += z0[q*4+0]*u2.x + z0[q*4+1]*u2.y + z0[q*4+2]*u2.z + z0[q*4+3]*u2.w;
                l1a += z1[q*4+0]*v0.x + z1[q*4+1]*v0.y + z1[q*4+2]*v0.z + z1[q*4+3]*v0.w;
                l1b += z1[q*4+0]*v2.x + z1[q*4+1]*v2.y + z1[q*4+2]*v2.z + z1[q*4+3]*v2.w;
            }
            float h0a=gelu_new(ca+l0a), h0b_=gelu_new(cb+l0b);
            float h1a=gelu_new(ca+l1a), h1b_=gelu_new(cb+l1b);
            size_t off = (size_t)n*F_DIM + f;
            *(float2*)&h_buf[off] = make_float2(h0a, h0b_);
            *(float2*)&h_buf[off + (size_t)N_TOK*F_DIM] = make_float2(h1a, h1b_);
            *(float2*)&g_buf[off] = make_float2(w0*h0a+w1w*h1a, w0*h0b_+w1w*h1b_);
        }
    }
}

// ============================================================================
// fc2 tf32: C = g @ W2^T, epilogue: + ws*b2 + z2 LoRA -> out
// ============================================================================
__global__ __launch_bounds__(256) void fc2_tf32(
    const float* __restrict__ W2, const float* __restrict__ b2,
    const float* __restrict__ B2, float* __restrict__ out)
{
    __shared__ __align__(16) float smem[10240];
    int bn = blockIdx.x, bm = blockIdx.y;
    int tid = threadIdx.x, wid = tid>>5, wr = wid&3, wc = wid>>2;
    TFC acc[2][4];

    gemm_tf32(acc, g_buf + (size_t)bm*128*F_DIM, W2 + (size_t)bn*128*F_DIM,
              F_DIM, F_DIM/16, smem);

    float* Cs = smem;
    for (int r = 0; r < 2; r++){
        __syncthreads();
        if ((wr >> 1) == r){
            int rl = (wr & 1) * 32;
#pragma unroll
            for (int i=0;i<2;i++)
#pragma unroll
            for (int j=0;j<4;j++)
                wmma::store_matrix_sync(Cs + (size_t)(rl+i*16)*136 + wc*64 + j*16,
                                        acc[i][j], 136, wmma::mem_row_major);
        }
        __syncthreads();

        int row_l = tid >> 2;
        int n = bm*128 + r*64 + row_l;
        int c0 = (tid & 3) * 32;
        float ws = wsum_buf[n];
        int e0 = eidx[2*n], e1 = eidx[2*n+1];
        float z0[8], z1[8];
#pragma unroll
        for (int q=0;q<8;q++){ z0[q]=z2s[n*16+q]; z1[q]=z2s[n*16+8+q]; }
        const float* crow = &Cs[(size_t)row_l*136];
        for (int jj = 0; jj < 32; jj++){
            int col = c0 + jj;
            int d = bn*128 + col;
            float c = crow[col] + ws*b2[d];
            const float4* q0 = (const float4*)&B2[((size_t)e0*D_DIM + d)*R_RANK];
            const float4* q1 = (const float4*)&B2[((size_t)e1*D_DIM + d)*R_RANK];
            float4 u0=q0[0], u1=q0[1], v0=q1[0], v1=q1[1];
            c += z0[0]*u0.x + z0[1]*u0.y + z0[2]*u0.z + z0[3]*u0.w
               + z0[4]*u1.x + z0[5]*u1.y + z0[6]*u1.z + z0[7]*u1.w;
            c += z1[0]*v0.x + z1[1]*v0.y + z1[2]*v0.z + z1[3]*v0.w
               + z1[4]*v1.x + z1[5]*v1.y + z1[6]*v1.z + z1[7]*v1.w;
            out[(size_t)n*D_DIM + d] = c;
        }
    }
}

// ============================================================================
// z2 — verbatim R1
// ============================================================================
__global__ __launch_bounds__(256) void z2_kernel(const float* __restrict__ A2)
{
    int n = blockIdx.x;
    int k = blockIdx.y;
    int tid = threadIdx.x;
    int e = eidx[2 * n + k];
    const float* h = h_buf + (size_t)k * N_TOK * F_DIM + (size_t)n * F_DIM;
    const float* a2 = A2 + (size_t)e * R_RANK * F_DIM;

    float acc[R_RANK];
#pragma unroll
    for (int r = 0; r < R_RANK; r++) acc[r] = 0.f;
    for (int f = tid * 4; f < F_DIM; f += 1024) {
        float4 hv = *(const float4*)(h + f);
#pragma unroll
        for (int r = 0; r < R_RANK; r++) {
            float4 av = *(const float4*)(a2 + (size_t)r * F_DIM + f);
            acc[r] += hv.x * av.x + hv.y * av.y + hv.z * av.z + hv.w * av.w;
        }
    }
    __shared__ float red[R_RANK][8];
#pragma unroll
    for (int r = 0; r < R_RANK; r++) {
        float v = acc[r];
        for (int o = 16; o > 0; o >>= 1) v += __shfl_down_sync(0xffffffffu, v, o);
        if ((tid & 31) == 0) red[r][tid >> 5] = v;
    }
    __syncthreads();
    if (tid < R_RANK) {
        float v = 0.f;
#pragma unroll
        for (int w = 0; w < 8; w++) v += red[tid][w];
        z2s[n * 16 + k * 8 + tid] = v * SCALING * ew[2 * n + k];
    }
}

// ============================================================================
// Verifiers + early-exit SIMT fallbacks (R1 kernels gated on flags)
// ============================================================================
__global__ void reset_kernel(){ gf1 = 0; gf2 = 0; }

__global__ __launch_bounds__(256) void ver_fc1(
    const float* __restrict__ x, const float* __restrict__ W1,
    const float* __restrict__ b1, const float* __restrict__ B1)
{
    int s = blockIdx.x, tid = threadIdx.x;
    int n = (s * 97) & (N_TOK - 1);
    int f = (s * 53 + 7) & (F_DIM - 1);
    float p = 0.f;
    for (int d = tid; d < D_DIM; d += 256)
        p += x[(size_t)n*D_DIM + d] * W1[(size_t)f*D_DIM + d];
    for (int o = 16; o > 0; o >>= 1) p += __shfl_down_sync(0xffffffffu, p, o);
    __shared__ float red[8];
    if ((tid & 31) == 0) red[tid >> 5] = p;
    __syncthreads();
    if (tid == 0){
        float c = b1[f];
#pragma unroll
        for (int w = 0; w < 8; w++) c += red[w];
        int e0 = eidx[2*n], e1 = eidx[2*n+1];
        float l0 = 0.f, l1 = 0.f;
#pragma unroll
        for (int r = 0; r < 8; r++){
            l0 += z1c[n*16+r]   * B1[((size_t)e0*F_DIM+f)*R_RANK + r];
            l1 += z1c[n*16+8+r] * B1[((size_t)e1*F_DIM+f)*R_RANK + r];
        }
        float h0 = gelu_new(c + l0), h1 = gelu_new(c + l1);
        float hg0 = h_buf[(size_t)n*F_DIM + f];
        float hg1 = h_buf[(size_t)N_TOK*F_DIM + (size_t)n*F_DIM + f];
        if (fabsf(hg0 - h0) > 1e-3f*fmaxf(1.f, fabsf(h0)) ||
            fabsf(hg1 - h1) > 1e-3f*fmaxf(1.f, fabsf(h1)))
            atomicAdd(&gf1, 1);
    }
}

__global__ __launch_bounds__(256) void ver_fc2(
    const float* __restrict__ b2, const float* __restrict__ B2,
    const float* __restrict__ out)
{
    int s = blockIdx.x, tid = threadIdx.x;
    int n = (s * 89 + 3) & (N_TOK - 1);
    int d = (s * 41 + 5) & (D_DIM - 1);
    float p = 0.f;
    for (int f = tid; f < F_DIM; f += 256)
        p += g_buf[(size_t)n*F_DIM + f] * __ldg(&((const float*)nullptr == nullptr ? b2 : b2)[0]) * 0.f
           + g_buf[(size_t)n*F_DIM + f] * 0.f;
    // (dummy zero to keep structure; real dot below)
    p = 0.f;
    for (int f = tid; f < F_DIM; f += 256)
        p += g_buf[(size_t)n*F_DIM + f] * 1.0f * 0.f;
    p = 0.f;
    {
        extern const float* w2_hack; // placeholder (unused)
    }
    // real computation uses W2 passed via out? -- replaced below
    (void)p;
    // NOTE: W2 passed through separate param in launcher version below.
    if (tid == 0) { }
}

// real ver_fc2 (separate to keep signature clean)
__global__ __launch_bounds__(256) void ver_fc2b(
    const float* __restrict__ W2, const float* __restrict__ b2,
    const float* __restrict__ B2, const float* __restrict__ out)
{
    int s = blockIdx.x, tid = threadIdx.x;
    int n = (s * 89 + 3) & (N_TOK - 1);
    int d = (s * 41 + 5) & (D_DIM - 1);
    float p = 0.f;
    for (int f = tid; f < F_DIM; f += 256)
        p += g_buf[(size_t)n*F_DIM + f] * W2[(size_t)d*F_DIM + f];
    for (int o = 16; o > 0; o >>= 1) p += __shfl_down_sync(0xffffffffu, p, o);
    __shared__ float red[8];
    if ((tid & 31) == 0) red[tid >> 5] = p;
    __syncthreads();
    if (tid == 0){
        float c = wsum_buf[n]*b2[d];
#pragma unroll
        for (int w = 0; w < 8; w++) c += red[w];
        int e0 = eidx[2*n], e1 = eidx[2*n+1];
#pragma unroll
        for (int r = 0; r < 8; r++){
            c += z2s[n*16+r]   * B2[((size_t)e0*D_DIM+d)*R_RANK + r];
            c += z2s[n*16+8+r] * B2[((size_t)e1*D_DIM+d)*R_RANK + r];
        }
        float o_ = out[(size_t)n*D_DIM + d];
        if (fabsf(o_ - c) > 1e-3f*fmaxf(1.f, fabsf(c)))
            atomicAdd(&gf2, 1);
    }
}

// Fallback fc1 — R1 kernel + early exit
__global__ __launch_bounds__(256, 2) void fc1_fb(
    const float* __restrict__ A, const float* __restrict__ B,
    const float* __restrict__ b1, const float* __restrict__ B1)
{
    if (gf1 == 0) return;
    const int K = D_DIM;
    int bn = blockIdx.x, bm = blockIdx.y;
    int tid = threadIdx.x;
    __shared__ float As[BK][BM + 4];
    __shared__ float Bs[BK][BN + 4];
    float acc[TM][TN];
#pragma unroll
    for (int i = 0; i < TM; i++)
#pragma unroll
        for (int j = 0; j < TN; j++) acc[i][j] = 0.f;
    int tx = tid % 16, ty = tid / 16;
    const float* Ab = A + (size_t)bm * BM * K;
    const float* Bb = B + (size_t)bn * BN * K;
    int rowL = tid >> 2;
    int colL = (tid & 3) * 4;
    for (int k0 = 0; k0 < K; k0 += BK) {
#pragma unroll
        for (int i = 0; i < 2; i++) {
            float4 a = *(const float4*)(Ab + (size_t)(rowL + i * 64) * K + k0 + colL);
            As[colL + 0][rowL + i * 64] = a.x;
            As[colL + 1][rowL + i * 64] = a.y;
            As[colL + 2][rowL + i * 64] = a.z;
            As[colL + 3][rowL + i * 64] = a.w;
            float4 b = *(const float4*)(Bb + (size_t)(rowL + i * 64) * K + k0 + colL);
            Bs[colL + 0][rowL + i * 64] = b.x;
            Bs[colL + 1][rowL + i * 64] = b.y;
            Bs[colL + 2][rowL + i * 64] = b.z;
            Bs[colL + 3][rowL + i * 64] = b.w;
        }
        __syncthreads();
#pragma unroll
        for (int kk = 0; kk < BK; kk++) {
            float4 a0 = *(const float4*)&As[kk][ty * TM];
            float4 a1 = *(const float4*)&As[kk][ty * TM + 4];
            float4 b0 = *(const float4*)&Bs[kk][tx * TN];
            float4 b1v = *(const float4*)&Bs[kk][tx * TN + 4];
            float ra[8] = {a0.x, a0.y, a0.z, a0.w, a1.x, a1.y, a1.z, a1.w};
            float rb[8] = {b0.x, b0.y, b0.z, b0.w, b1v.x, b1v.y, b1v.z, b1v.w};
#pragma unroll
            for (int i = 0; i < TM; i++)
#pragma unroll
                for (int j = 0; j < TN; j++) acc[i][j] += ra[i] * rb[j];
        }
        __syncthreads();
    }
    int nrow0 = bm * BM + ty * TM;
    int fcol0 = bn * BN + tx * TN;
#pragma unroll
    for (int i = 0; i < TM; i++) {
        int n = nrow0 + i;
        int e0 = eidx[2 * n], e1 = eidx[2 * n + 1];
        float w0 = ew[2 * n], w1 = ew[2 * n + 1];
        const float4* zp = (const float4*)&z1c[n * 16];
        float4 z0a = zp[0], z0b = zp[1], z1a = zp[2], z1b = zp[3];
        float h0v[TN], h1v[TN], gv[TN];
#pragma unroll
        for (int j = 0; j < TN; j++) {
            int f = fcol0 + j;
            float c = acc[i][j] + b1[f];
            const float4* q0 = (const float4*)&B1[((size_t)e0 * F_DIM + f) * R_RANK];
            float4 u0 = q0[0], u1 = q0[1];
            float l0 = z0a.x * u0.x + z0a.y * u0.y + z0a.z * u0.z + z0a.w * u0.w
                     + z0b.x * u1.x + z0b.y * u1.y + z0b.z * u1.z + z0b.w * u1.w;
            const float4* q1 = (const float4*)&B1[((size_t)e1 * F_DIM + f) * R_RANK];
            float4 v0 = q1[0], v1 = q1[1];
            float l1 = z1a.x * v0.x + z1a.y * v0.y + z1a.z * v0.z + z1a.w * v0.w
                     + z1b.x * v1.x + z1b.y * v1.y + z1b.z * v1.z + z1b.w * v1.w;
            float h0 = gelu_new(c + l0);
            float h1 = gelu_new(c + l1);
            h0v[j] = h0; h1v[j] = h1;
            gv[j] = w0 * h0 + w1 * h1;
        }
        size_t off = (size_t)n * F_DIM + fcol0;
        *(float4*)&h_buf[off]     = make_float4(h0v[0], h0v[1], h0v[2], h0v[3]);
        *(float4*)&h_buf[off + 4] = make_float4(h0v[4], h0v[5], h0v[6], h0v[7]);
        size_t off1 = off + (size_t)N_TOK * F_DIM;
        *(float4*)&h_buf[off1]     = make_float4(h1v[0], h1v[1], h1v[2], h1v[3]);
        *(float4*)&h_buf[off1 + 4] = make_float4(h1v[4], h1v[5], h1v[6], h1v[7]);
        *(float4*)&g_buf[off]     = make_float4(gv[0], gv[1], gv[2], gv[3]);
        *(float4*)&g_buf[off + 4] = make_float4(gv[4], gv[5], gv[6], gv[7]);
    }
}

// Fallback fc2 — R1 kernel + early exit
__global__ __launch_bounds__(256, 2) void fc2_fb(
    const float* __restrict__ B, const float* __restrict__ b2,
    const float* __restrict__ B2, float* __restrict__ out)
{
    if (gf2 == 0 && gf1 == 0) return;
    const int K = F_DIM;
    int bn = blockIdx.x, bm = blockIdx.y;
    int tid = threadIdx.x;
    __shared__ float As[BK][BM + 4];
    __shared__ float Bs[BK][BN + 4];
    float acc[TM][TN];
#pragma unroll
    for (int i = 0; i < TM; i++)
#pragma unroll
        for (int j = 0; j < TN; j++) acc[i][j] = 0.f;
    int tx = tid % 16, ty = tid / 16;
    const float* Ab = g_buf + (size_t)bm * BM * K;
    const float* Bb = B + (size_t)bn * BN * K;
    int rowL = tid >> 2;
    int colL = (tid & 3) * 4;
    for (int k0 = 0; k0 < K; k0 += BK) {
#pragma unroll
        for (int i = 0; i < 2; i++) {
            float4 a = *(const float4*)(Ab + (size_t)(rowL + i * 64) * K + k0 + colL);
            As[colL + 0][rowL + i * 64] = a.x;
            As[colL + 1][rowL + i * 64] = a.y;
            As[colL + 2][rowL + i * 64] = a.z;
            As[colL + 3][rowL + i * 64] = a.w;
            float4 b = *(const float4*)(Bb + (size_t)(rowL + i * 64) * K + k0 + colL);
            Bs[colL + 0][rowL + i * 64] = b.x;
            Bs[colL + 1][rowL + i * 64] = b.y;
            Bs[colL + 2][rowL + i * 64] = b.z;
            Bs[colL + 3][rowL + i * 64] = b.w;
        }
        __syncthreads();
#pragma unroll
        for (int kk = 0; kk < BK; kk++) {
            float4 a0 = *(const float4*)&As[kk][ty * TM];
            float4 a1 = *(const float4*)&As[kk][ty * TM + 4];
            float4 b0 = *(const float4*)&Bs[kk][tx * TN];
            float4 b1v = *(const float4*)&Bs[kk][tx * TN + 4];
            float ra[8] = {a0.x, a0.y, a0.z, a0.w, a1.x, a1.y, a1.z, a1.w};
            float rb[8] = {b0.x, b0.y, b0.z, b0.w, b1v.x, b1v.y, b1v.z, b1v.w};
#pragma unroll
            for (int i = 0; i < TM; i++)
#pragma unroll
                for (int j = 0; j < TN; j++) acc[i][j] += ra[i] * rb[j];
        }
        __syncthreads();
    }
    int nrow0 = bm * BM + ty * TM;
    int dcol0 = bn * BN + tx * TN;
#pragma unroll
    for (int i = 0; i < TM; i++) {
        int n = nrow0 + i;
        float ws = wsum_buf[n];
        int e0 = eidx[2 * n], e1 = eidx[2 * n + 1];
        const float4* zp = (const float4*)&z2s[n * 16];
        float4 z0a = zp[0], z0b = zp[1], z1a = zp[2], z1b = zp[3];
        float ov[TN];
#pragma unroll
        for (int j = 0; j < TN; j++) {
            int d = dcol0 + j;
            float c = acc[i][j] + ws * b2[d];
            const float4* q0 = (const float4*)&B2[((size_t)e0 * D_DIM + d) * R_RANK];
            float4 u0 = q0[0], u1 = q0[1];
            c += z0a.x * u0.x + z0a.y * u0.y + z0a.z * u0.z + z0a.w * u0.w
               + z0b.x * u1.x + z0b.y * u1.y + z0b.z * u1.z + z0b.w * u1.w;
            const float4* q1 = (const float4*)&B2[((size_t)e1 * D_DIM + d) * R_RANK];
            float4 v0 = q1[0], v1 = q1[1];
            c += z1a.x * v0.x + z1a.y * v0.y + z1a.z * v0.z + z1a.w * v0.w
               + z1b.x * v1.x + z1b.y * v1.y + z1b.z * v1.z + z1b.w * v1.w;
            ov[j] = c;
        }
        size_t off = (size_t)n * D_DIM + dcol0;
        *(float4*)&out[off]     = make_float4(ov[0], ov[1], ov[2], ov[3]);
        *(float4*)&out[off + 4] = make_float4(ov[4], ov[5], ov[6], ov[7]);
    }
}

// ------------------------- launch ------------------------------------------
extern "C" void kernel_launch(void* const* d_in, const int* in_sizes, int n_in,
                              void* d_out, int out_size)
{
    (void)in_sizes; (void)n_in; (void)out_size;
    const float* x  = (const float*)d_in[0];
    const float* Wr = (const float*)d_in[1];
    const float* br = (const float*)d_in[2];
    const float* W1 = (const float*)d_in[3];
    const float* b1 = (const float*)d_in[4];
    const float* W2 = (const float*)d_in[5];
    const float* b2 = (const float*)d_in[6];
    const float* A1 = (const float*)d_in[7];
    const float* B1 = (const float*)d_in[8];
    const float* A2 = (const float*)d_in[9];
    const float* B2 = (const float*)d_in[10];
    float* out = (float*)d_out;

    reset_kernel<<<1, 1>>>();
    router_kernel<<<N_TOK, 256>>>(x, Wr, br, A1);

    // fc1 on tensor cores (tf32 x3), then verify + gated SIMT fallback
    fc1_tf32<<<dim3(F_DIM/128, N_TOK/128), 256>>>(x, W1, b1, B1);
    ver_fc1<<<1024, 256>>>(x, W1, b1, B1);
    fc1_fb<<<dim3(F_DIM/BN, N_TOK/BM), 256>>>(x, W1, b1, B1);

    z2_kernel<<<dim3(N_TOK, 2), 256>>>(A2);

    // fc2 on tensor cores (tf32 x3), then verify + gated SIMT fallback
    fc2_tf32<<<dim3(D_DIM/128, N_TOK/128), 256>>>(W2, b2, B2, out);
    ver_fc2b<<<512, 256>>>(W2, b2, B2, out);
    fc2_fb<<<dim3(D_DIM/BN, N_TOK/BM), 256>>>(W2, b2, B2, out);
}